// round 14
// baseline (speedup 1.0000x reference)
#include <cuda_runtime.h>
#include <cuda_bf16.h>
#include <cstdint>

#define Bb 4
#define Tt 2048
#define Ee 1024
#define HD 64
#define Mrows (Bb*Tt)
#define FPAD 40   // u32 row stride for LDS.64 kernels
#define OPAD 36   // outproj LDS.32 unpermuted layout
// Q pre-scale: (1/sqrt(64)) * log2(e), so softmax is a bare exp2
#define QSCALE 0.1803368801111244f
// pair-permute within each 8-block: c -> 2*(c%4) + (c>=4), so (c, c+4) adjacent
#define PC(c) (((c) & ~7) | (((c) & 3) << 1) | (((c) >> 2) & 1))

// scratch (no cudaMalloc allowed)
__device__ __align__(16) uint32_t g_qh[Mrows*32];   // permuted cols, bf16 hi
__device__ __align__(16) uint32_t g_ql[Mrows*32];   // permuted cols, bf16 lo
__device__ __align__(16) uint32_t g_kh[Mrows*32];   // permuted
__device__ __align__(16) uint32_t g_kl[Mrows*32];   // permuted
__device__ __align__(16) uint32_t g_vth[Mrows*32];  // permuted V^T tiles [tile][hd][s2]
__device__ __align__(16) uint32_t g_vtl[Mrows*32];
__device__ __align__(16) uint32_t g_wbh[192*512];   // permuted
__device__ __align__(16) uint32_t g_wbl[192*512];   // permuted
__device__ __align__(16) uint32_t g_wrh[1024*32];   // UNpermuted (outproj)
__device__ __align__(16) uint32_t g_wrl[1024*32];
__device__ __align__(16) float g_po[Mrows*HD];      // SINGLE accumulator (red.add)
__device__ __align__(16) float g_pl[Mrows];

// ---------------------------------------------------------------------------
__device__ __forceinline__ void mma_bf16(float4& c,
                                         uint32_t a0, uint32_t a1, uint32_t a2, uint32_t a3,
                                         uint32_t b0, uint32_t b1) {
    asm volatile(
        "mma.sync.aligned.m16n8k16.row.col.f32.bf16.bf16.f32 "
        "{%0,%1,%2,%3}, {%4,%5,%6,%7}, {%8,%9}, {%0,%1,%2,%3};"
        : "+f"(c.x), "+f"(c.y), "+f"(c.z), "+f"(c.w)
        : "r"(a0), "r"(a1), "r"(a2), "r"(a3), "r"(b0), "r"(b1));
}

__device__ __forceinline__ void bsplit2(float a0, float a1, uint32_t& h, uint32_t& l) {
    __nv_bfloat162 hh = __floats2bfloat162_rn(a0, a1);
    float r0 = a0 - __bfloat162float(hh.x);
    float r1 = a1 - __bfloat162float(hh.y);
    __nv_bfloat162 ll = __floats2bfloat162_rn(r0, r1);
    h = *reinterpret_cast<uint32_t*>(&hh);
    l = *reinterpret_cast<uint32_t*>(&ll);
}

__device__ __forceinline__ float ex2(float x) {
    float y;
    asm("ex2.approx.ftz.f32 %0, %1;" : "=f"(y) : "f"(x));
    return y;
}

__device__ __forceinline__ void cp16(uint32_t dst, const void* src) {
    asm volatile("cp.async.cg.shared.global [%0], [%1], 16;" :: "r"(dst), "l"(src));
}
__device__ __forceinline__ void cp_commit() {
    asm volatile("cp.async.commit_group;");
}
__device__ __forceinline__ void cp_wait0() {
    asm volatile("cp.async.wait_group 0;");
}

// ---------------------------------------------------------------------------
// Kernel 0: pre-split weights (permuted) + fold W_out + ZERO po/pl accumulators
// ---------------------------------------------------------------------------
__global__ void prep_kernel(const float* __restrict__ Wq, const float* __restrict__ Wk,
                            const float* __restrict__ Wv, const float* __restrict__ Wout) {
    int idx = blockIdx.x * 256 + threadIdx.x;
    if (idx < 98304) {
        int n = idx >> 9, k2 = idx & 511;
        const float* w = (n < 64) ? Wq : ((n < 128) ? Wk : Wv);
        int r = n & 63;
        float a0 = w[(size_t)r * 1024 + 2 * k2];
        float a1 = w[(size_t)r * 1024 + 2 * k2 + 1];
        uint32_t h, l; bsplit2(a0, a1, h, l);
        int pidx = (n << 9) | PC(k2);
        g_wbh[pidx] = h; g_wbl[pidx] = l;
    } else if (idx < 131072) {
        int j = idx - 98304;
        int o = j >> 5, d2 = j & 31;
        float s0 = 0.f, s1 = 0.f;
#pragma unroll
        for (int h = 0; h < 16; h++) {
            s0 += Wout[(size_t)o * 1024 + h * 64 + 2 * d2];
            s1 += Wout[(size_t)o * 1024 + h * 64 + 2 * d2 + 1];
        }
        uint32_t h, l; bsplit2(s0, s1, h, l);
        g_wrh[j] = h; g_wrl[j] = l;
    } else {
        int z = idx - 131072;
        float4 zero = make_float4(0.f, 0.f, 0.f, 0.f);
        if (z < 131072) ((float4*)g_po)[z] = zero;
        else            ((float4*)g_pl)[z - 131072] = zero;
    }
}

// ---------------------------------------------------------------------------
// Kernel 1: fused QKV (grid 128, CTA 64 rows x 192 cols, block 1024 = 32 warps
// in 4m x 8col, warp = 16r x 24c, nb=3). LDS.64 fragments, permuted layout.
// V transpose+split fused in epilogue.
// ---------------------------------------------------------------------------
#define QKV_ABUF (2*64*FPAD)
#define QKV_BBUF (2*192*FPAD)
#define QKV_B0   (2*QKV_ABUF)
#define QKV_SMEM ((2*QKV_ABUF + 2*QKV_BBUF) * 4)
#define VSTR 66   // f32 stride of the staged V tile

__global__ void __launch_bounds__(1024) qkv_fused(const float* __restrict__ emb) {
    extern __shared__ uint32_t smu[];
    const uint32_t sb = (uint32_t)__cvta_generic_to_shared(smu);

    const int m0 = blockIdx.x * 64;
    const int tid = threadIdx.x;
    const int lane = tid & 31;
    const int w = tid >> 5;
    const int wm = (w & 3) * 16;
    const int colbase = (w >> 2) * 24;
    const int g = lane >> 2, q = lane & 3;

    float4 acc[3];
#pragma unroll
    for (int nb = 0; nb < 3; nb++) acc[nb] = make_float4(0.f, 0.f, 0.f, 0.f);

    // A LDG mapping: exactly 1 float4/thread (64 rows x 16 float4)
    const int arow = tid >> 4, ac = tid & 15;

    float4 aR = *(const float4*)(emb + (size_t)(m0 + arow) * Ee + ac * 4);
    // B prologue: 3072 uint4 (hi 1536 + lo 1536) -> 3 per thread
#pragma unroll
    for (int i = 0; i < 3; i++) {
        int jj = tid + i * 1024;
        int half = jj >= 1536;
        int rem = jj - half * 1536;
        int row = rem >> 3, c = rem & 7;
        const uint32_t* gp = half ? g_wbl : g_wbh;
        uint32_t dst = sb + (QKV_B0 + half * 192 * FPAD + row * FPAD + c * 4) * 4;
        cp16(dst, gp + (size_t)row * 512 + c * 4);
    }
    cp_commit();

    for (int kt = 0; kt < 16; kt++) {
        const int buf = kt & 1;
        uint32_t* Ah = smu + buf * QKV_ABUF;
        uint32_t* Al = Ah + 64 * FPAD;
        uint32_t* Bh = smu + QKV_B0 + buf * QKV_BBUF;
        uint32_t* Bl = Bh + 192 * FPAD;

        {   // store prefetched A reg (permuted u32 cols)
            uint32_t h0, l0, h1, l1;
            const int p0 = PC(2 * ac), p1 = PC(2 * ac + 1);
            bsplit2(aR.x, aR.y, h0, l0);
            bsplit2(aR.z, aR.w, h1, l1);
            Ah[arow * FPAD + p0] = h0; Ah[arow * FPAD + p1] = h1;
            Al[arow * FPAD + p0] = l0; Al[arow * FPAD + p1] = l1;
        }
        cp_wait0();
        __syncthreads();

        if (kt < 15) {
            const int kn = (kt + 1) * 64;
            aR = *(const float4*)(emb + (size_t)(m0 + arow) * Ee + kn + ac * 4);
            const int nbuf = buf ^ 1;
#pragma unroll
            for (int i = 0; i < 3; i++) {
                int jj = tid + i * 1024;
                int half = jj >= 1536;
                int rem = jj - half * 1536;
                int row = rem >> 3, c = rem & 7;
                const uint32_t* gp = half ? g_wbl : g_wbh;
                uint32_t dst = sb + (QKV_B0 + nbuf * QKV_BBUF
                                     + half * 192 * FPAD + row * FPAD + c * 4) * 4;
                cp16(dst, gp + (size_t)row * 512 + (kt + 1) * 32 + c * 4);
            }
            cp_commit();
        }

#pragma unroll
        for (int ks = 0; ks < 4; ks++) {
            const int kb2 = ks * 8 + 2 * q;
            uint2 a_h0 = *(const uint2*)&Ah[(wm + g) * FPAD + kb2];
            uint2 a_h1 = *(const uint2*)&Ah[(wm + g + 8) * FPAD + kb2];
            uint2 a_l0 = *(const uint2*)&Al[(wm + g) * FPAD + kb2];
            uint2 a_l1 = *(const uint2*)&Al[(wm + g + 8) * FPAD + kb2];
#pragma unroll
            for (int nb = 0; nb < 3; nb++) {
                const int n = colbase + nb * 8 + g;
                uint2 bh = *(const uint2*)&Bh[n * FPAD + kb2];
                uint2 bl = *(const uint2*)&Bl[n * FPAD + kb2];
                mma_bf16(acc[nb], a_h0.x, a_h1.x, a_h0.y, a_h1.y, bh.x, bh.y);
                mma_bf16(acc[nb], a_h0.x, a_h1.x, a_h0.y, a_h1.y, bl.x, bl.y);
                mma_bf16(acc[nb], a_l0.x, a_l1.x, a_l0.y, a_l1.y, bh.x, bh.y);
            }
        }
        __syncthreads();
    }

    // epilogue: Q/K -> gmem (hi+lo, permuted); V -> smem stage
    float* Vsm = (float*)smu;
    const size_t r0 = m0 + wm + g;
    const int rowl = wm + g;
#pragma unroll
    for (int nb = 0; nb < 3; nb++) {
        int gcol = colbase + nb * 8 + 2 * q;
        int sec = gcol >> 6;
        int lc = gcol & 63;
        int pj = PC(lc >> 1);
        float4 c = acc[nb];
        if (sec == 0) {          // Q: hi+lo, pre-scaled into log2 domain
            uint32_t h, l;
            bsplit2(c.x * QSCALE, c.y * QSCALE, h, l);
            g_qh[r0 * 32 + pj] = h; g_ql[r0 * 32 + pj] = l;
            bsplit2(c.z * QSCALE, c.w * QSCALE, h, l);
            g_qh[(r0 + 8) * 32 + pj] = h; g_ql[(r0 + 8) * 32 + pj] = l;
        } else if (sec == 1) {   // K: hi+lo, permuted cols
            uint32_t h, l;
            bsplit2(c.x, c.y, h, l);
            g_kh[r0 * 32 + pj] = h; g_kl[r0 * 32 + pj] = l;
            bsplit2(c.z, c.w, h, l);
            g_kh[(r0 + 8) * 32 + pj] = h; g_kl[(r0 + 8) * 32 + pj] = l;
        } else {                 // V: stage f32 transposed in smem
            Vsm[lc * VSTR + rowl]           = c.x;
            Vsm[(lc + 1) * VSTR + rowl]     = c.y;
            Vsm[lc * VSTR + rowl + 8]       = c.z;
            Vsm[(lc + 1) * VSTR + rowl + 8] = c.w;
        }
    }
    __syncthreads();

    // cooperative V^T split: tile = blockIdx.x, 2048 u32 -> 2 per thread
#pragma unroll
    for (int i = 0; i < 2; i++) {
        int j = tid + i * 1024;
        int hd = j >> 5, s2 = j & 31;
        float v0 = Vsm[hd * VSTR + 2 * s2];
        float v1 = Vsm[hd * VSTR + 2 * s2 + 1];
        uint32_t h, l; bsplit2(v0, v1, h, l);
        int pidx = (blockIdx.x << 11) | (hd << 5) | PC(s2);
        g_vth[pidx] = h;
        g_vtl[pidx] = l;
    }
}

// ---------------------------------------------------------------------------
// Kernel 2: flash attention. 3xBF16 QK^T and PV, BQ=128, balanced variable
// split-KV (qt gets qt/2+1 parts, each <= 4 kv-tiles; grid (72,4) = one wave).
// Partials exactly additive (no-max softmax) -> RED.ADD into g_po/g_pl.
// ---------------------------------------------------------------------------
#define FL_KVBUF (4*64*FPAD)
#define FL_SMEM  ((2*FL_KVBUF) * 4)

__device__ __forceinline__ void fl_prefetch(uint32_t sb, int bufoff, size_t gbase, int tid) {
#pragma unroll
    for (int i = 0; i < 8; i++) {
        const uint32_t* gp = (i < 2) ? g_kh : (i < 4) ? g_kl : (i < 6) ? g_vth : g_vtl;
        int rem = tid + (i & 1) * 256;
        int row = rem >> 3, c = rem & 7;
        uint32_t dst = sb + (bufoff + (i >> 1) * (64 * FPAD) + row * FPAD + c * 4) * 4;
        cp16(dst, gp + gbase + rem * 4);
    }
}

__global__ void __launch_bounds__(256, 2) flash_mma() {
    extern __shared__ uint32_t smu[];
    const uint32_t sb = (uint32_t)__cvta_generic_to_shared(smu);

    const int b = blockIdx.y;
    int bid = blockIdx.x;
    int qt = 0, P = 1;
    while (bid >= P) { bid -= P; qt++; P = (qt >> 1) + 1; }
    const int part = bid;
    const int q0 = qt * 128;
    const int tid = threadIdx.x;
    const int lane = tid & 31;
    const int wm = (tid >> 5) * 16;
    const int g = lane >> 2, q = lane & 3;

    const int nt = 2 * qt + 2;
    const int t_begin = (part * nt) / P;
    const int t_end = ((part + 1) * nt) / P;

    const size_t qrow0 = (size_t)b * Tt + q0;
    uint32_t qh[4][4], ql[4][4];
#pragma unroll
    for (int ks = 0; ks < 4; ks++) {
        const int kb2 = ks * 8 + 2 * q;
        uint2 t0 = *(const uint2*)&g_qh[(qrow0 + wm + g) * 32 + kb2];
        uint2 t1 = *(const uint2*)&g_qh[(qrow0 + wm + g + 8) * 32 + kb2];
        qh[ks][0] = t0.x; qh[ks][2] = t0.y;
        qh[ks][1] = t1.x; qh[ks][3] = t1.y;
        uint2 u0 = *(const uint2*)&g_ql[(qrow0 + wm + g) * 32 + kb2];
        uint2 u1 = *(const uint2*)&g_ql[(qrow0 + wm + g + 8) * 32 + kb2];
        ql[ks][0] = u0.x; ql[ks][2] = u0.y;
        ql[ks][1] = u1.x; ql[ks][3] = u1.y;
    }

    float l0r = 0.f, l1r = 0.f;
    float4 o[8];
#pragma unroll
    for (int nb = 0; nb < 8; nb++) o[nb] = make_float4(0.f, 0.f, 0.f, 0.f);

    fl_prefetch(sb, 0, ((size_t)b * Tt + t_begin * 64) * 32, tid);
    cp_commit();

    int buf = 0;
    for (int t = t_begin; t < t_end; t++) {
        const int k0 = t * 64;
        cp_wait0();
        __syncthreads();
        if (t + 1 < t_end) {
            fl_prefetch(sb, (buf ^ 1) * FL_KVBUF, ((size_t)b * Tt + (t + 1) * 64) * 32, tid);
            cp_commit();
        }
        uint32_t* Kh  = smu + buf * FL_KVBUF;
        uint32_t* Kl  = Kh + 64 * FPAD;
        uint32_t* Vth = Kh + 2 * 64 * FPAD;
        uint32_t* Vtl = Kh + 3 * 64 * FPAD;

        // S = Q K^T  (3x: qh*kh + qh*kl + ql*kh)
        float4 s[8];
#pragma unroll
        for (int nb = 0; nb < 8; nb++) s[nb] = make_float4(0.f, 0.f, 0.f, 0.f);
#pragma unroll
        for (int ks = 0; ks < 4; ks++) {
            const int kb2 = ks * 8 + 2 * q;
#pragma unroll
            for (int nb = 0; nb < 8; nb++) {
                const int n = nb * 8 + g;
                uint2 kh = *(const uint2*)&Kh[n * FPAD + kb2];
                uint2 kl = *(const uint2*)&Kl[n * FPAD + kb2];
                mma_bf16(s[nb], qh[ks][0], qh[ks][1], qh[ks][2], qh[ks][3], kh.x, kh.y);
                mma_bf16(s[nb], qh[ks][0], qh[ks][1], qh[ks][2], qh[ks][3], kl.x, kl.y);
                mma_bf16(s[nb], ql[ks][0], ql[ks][1], ql[ks][2], ql[ks][3], kh.x, kh.y);
            }
        }

        // causal mask
        if (k0 + 63 > q0 + wm) {
            const int r0g = q0 + wm + g;
#pragma unroll
            for (int nb = 0; nb < 8; nb++) {
                int c = k0 + nb * 8 + 2 * q;
                if (c > r0g)         s[nb].x = -1e30f;
                if (c + 1 > r0g)     s[nb].y = -1e30f;
                if (c > r0g + 8)     s[nb].z = -1e30f;
                if (c + 1 > r0g + 8) s[nb].w = -1e30f;
            }
        }

        // p = exp2(s) via MUFU.EX2; per-lane row sums (reduced in epilogue)
#pragma unroll
        for (int nb = 0; nb < 8; nb++) {
            s[nb].x = ex2(s[nb].x);
            s[nb].y = ex2(s[nb].y);
            s[nb].z = ex2(s[nb].z);
            s[nb].w = ex2(s[nb].w);
            l0r += s[nb].x + s[nb].y;
            l1r += s[nb].z + s[nb].w;
        }

        // O += P V  (3x: ph*vh + ph*vl + pl*vh), P packed from S regs
#pragma unroll
        for (int ks = 0; ks < 4; ks++) {
            uint32_t ph0, pl0, ph1, pl1, ph2, pl2, ph3, pl3;
            bsplit2(s[2 * ks].x,     s[2 * ks].y,     ph0, pl0);
            bsplit2(s[2 * ks].z,     s[2 * ks].w,     ph1, pl1);
            bsplit2(s[2 * ks + 1].x, s[2 * ks + 1].y, ph2, pl2);
            bsplit2(s[2 * ks + 1].z, s[2 * ks + 1].w, ph3, pl3);
            const int kb2 = ks * 8 + 2 * q;
#pragma unroll
            for (int nb = 0; nb < 8; nb++) {
                const int n = nb * 8 + g;
                uint2 vh = *(const uint2*)&Vth[n * FPAD + kb2];
                uint2 vl = *(const uint2*)&Vtl[n * FPAD + kb2];
                mma_bf16(o[nb], ph0, ph1, ph2, ph3, vh.x, vh.y);
                mma_bf16(o[nb], ph0, ph1, ph2, ph3, vl.x, vl.y);
                mma_bf16(o[nb], pl0, pl1, pl2, pl3, vh.x, vh.y);
            }
        }
        buf ^= 1;
    }

    // epilogue: reduce l once, RED.ADD partials into the single accumulator
    l0r += __shfl_xor_sync(0xffffffffu, l0r, 1);
    l0r += __shfl_xor_sync(0xffffffffu, l0r, 2);
    l1r += __shfl_xor_sync(0xffffffffu, l1r, 1);
    l1r += __shfl_xor_sync(0xffffffffu, l1r, 2);

    const size_t row0 = (size_t)b * Tt + q0 + wm + g;
#pragma unroll
    for (int nb = 0; nb < 8; nb++) {
        int col = nb * 8 + 2 * q;
        atomicAdd(g_po + row0 * HD + col,           o[nb].x);
        atomicAdd(g_po + row0 * HD + col + 1,       o[nb].y);
        atomicAdd(g_po + (row0 + 8) * HD + col,     o[nb].z);
        atomicAdd(g_po + (row0 + 8) * HD + col + 1, o[nb].w);
    }
    if (q == 0) {
        atomicAdd(g_pl + row0, l0r);
        atomicAdd(g_pl + row0 + 8, l1r);
    }
}

// ---------------------------------------------------------------------------
// Kernel 3: out-proj 3xBF16 with fused normalize+split.
// CTA 128x256, block 1024 = 32 warps (8m x 4col), warp = 16r x 64c, nb=8.
// grid (64,4) = 256 CTAs.
// ---------------------------------------------------------------------------
#define OUTP_SMEM ((2*128*OPAD + 2*256*OPAD) * 4)

__global__ void __launch_bounds__(1024) outproj_mma(float* __restrict__ out) {
    extern __shared__ uint32_t smu[];
    uint32_t* Ah = smu;
    uint32_t* Al = Ah + 128 * OPAD;
    uint32_t* Bh = Al + 128 * OPAD;
    uint32_t* Bl = Bh + 256 * OPAD;

    const int m0 = blockIdx.x * 128, n0 = blockIdx.y * 256;
    const int tid = threadIdx.x;
    const int lane = tid & 31;
    const int w = tid >> 5;
    const int wm = (w & 7) * 16;
    const int ncb = (w >> 3) * 64;
    const int g = lane >> 2, q = lane & 3;

    // A: normalize po -> bf16 hi/lo split -> smem. 8 threads/row, 8 cols each.
    {
        const int arow = tid >> 3;
        const int aseg = (tid & 7) * 8;
        float inv = 1.f / g_pl[m0 + arow];
        const float* src = g_po + (size_t)(m0 + arow) * HD + aseg;
#pragma unroll
        for (int j = 0; j < 2; j++) {
            float4 v = *(const float4*)(src + j * 4);
            uint32_t h0, l0, h1, l1;
            bsplit2(v.x * inv, v.y * inv, h0, l0);
            bsplit2(v.z * inv, v.w * inv, h1, l1);
            int c2 = (aseg >> 1) + j * 2;
            *(uint2*)&Ah[arow * OPAD + c2] = make_uint2(h0, h1);
            *(uint2*)&Al[arow * OPAD + c2] = make_uint2(l0, l1);
        }
    }
    // B: 4096 uint4 (hi 2048 + lo 2048) -> 4 per thread
#pragma unroll
    for (int i = 0; i < 4; i++) {
        int j = tid + i * 1024;
        int half = j >= 2048;
        int rem = j - half * 2048;
        int row = rem >> 3, c = rem & 7;
        const uint32_t* gp = half ? g_wrl : g_wrh;
        uint32_t* dp = half ? Bl : Bh;
        *(uint4*)(dp + row * OPAD + c * 4) = *(const uint4*)(gp + (size_t)(n0 + row) * 32 + c * 4);
    }
    __syncthreads();

    float4 acc[8];
#pragma unroll
    for (int nb = 0; nb < 8; nb++) acc[nb] = make_float4(0.f, 0.f, 0.f, 0.f);

#pragma unroll
    for (int ks = 0; ks < 4; ks++) {
        const int kb = ks * 8 + q;
        uint32_t ah0 = Ah[(wm + g) * OPAD + kb];
        uint32_t ah1 = Ah[(wm + g + 8) * OPAD + kb];
        uint32_t ah2 = Ah[(wm + g) * OPAD + kb + 4];
        uint32_t ah3 = Ah[(wm + g + 8) * OPAD + kb + 4];
        uint32_t al0 = Al[(wm + g) * OPAD + kb];
        uint32_t al1 = Al[(wm + g + 8) * OPAD + kb];
        uint32_t al2 = Al[(wm + g) * OPAD + kb + 4];
        uint32_t al3 = Al[(wm + g + 8) * OPAD + kb + 4];
#pragma unroll
        for (int nb = 0; nb < 8; nb++) {
            const int n = ncb + nb * 8 + g;
            uint32_t bh0 = Bh[n * OPAD + kb];
            uint32_t bh1 = Bh[n * OPAD + kb + 4];
            uint32_t bl0 = Bl[n * OPAD + kb];
            uint32_t bl1 = Bl[n * OPAD + kb + 4];
            mma_bf16(acc[nb], ah0, ah1, ah2, ah3, bh0, bh1);
            mma_bf16(acc[nb], ah0, ah1, ah2, ah3, bl0, bl1);
            mma_bf16(acc[nb], al0, al1, al2, al3, bh0, bh1);
        }
    }

    const int row0 = m0 + wm + g;
#pragma unroll
    for (int nb = 0; nb < 8; nb++) {
        int col = n0 + ncb + nb * 8 + 2 * q;
        *(float2*)(out + (size_t)row0 * 1024 + col)       = make_float2(acc[nb].x, acc[nb].y);
        *(float2*)(out + (size_t)(row0 + 8) * 1024 + col) = make_float2(acc[nb].z, acc[nb].w);
    }
}

// ---------------------------------------------------------------------------
extern "C" void kernel_launch(void* const* d_in, const int* in_sizes, int n_in,
                              void* d_out, int out_size) {
    (void)in_sizes; (void)n_in; (void)out_size;
    const float* emb  = (const float*)d_in[0];
    const float* Wq   = (const float*)d_in[1];
    const float* Wk   = (const float*)d_in[2];
    const float* Wv   = (const float*)d_in[3];
    const float* Wout = (const float*)d_in[4];
    float* out = (float*)d_out;

    prep_kernel<<<1032, 256>>>(Wq, Wk, Wv, Wout);

    cudaFuncSetAttribute(qkv_fused, cudaFuncAttributeMaxDynamicSharedMemorySize, QKV_SMEM);
    qkv_fused<<<128, 1024, QKV_SMEM>>>(emb);

    cudaFuncSetAttribute(flash_mma, cudaFuncAttributeMaxDynamicSharedMemorySize, FL_SMEM);
    flash_mma<<<dim3(72, 4), 256, FL_SMEM>>>();

    cudaFuncSetAttribute(outproj_mma, cudaFuncAttributeMaxDynamicSharedMemorySize, OUTP_SMEM);
    outproj_mma<<<dim3(64, 4), 1024, OUTP_SMEM>>>(out);
}

// round 15
// speedup vs baseline: 1.0201x; 1.0201x over previous
#include <cuda_runtime.h>
#include <cuda_bf16.h>
#include <cstdint>

#define Bb 4
#define Tt 2048
#define Ee 1024
#define HD 64
#define Mrows (Bb*Tt)
#define FPAD 40   // u32 row stride for LDS.64 kernels: (8g+2q)%32 distinct per 16-lane phase
// Q pre-scale: (1/sqrt(64)) * log2(e), so softmax is a bare exp2
#define QSCALE 0.1803368801111244f
// pair-permute within each 8-block: c -> 2*(c%4) + (c>=4), so (c, c+4) adjacent
#define PC(c) (((c) & ~7) | (((c) & 3) << 1) | (((c) >> 2) & 1))

// scratch (no cudaMalloc allowed)
__device__ __align__(16) uint32_t g_qh[Mrows*32];   // permuted cols, bf16 hi
__device__ __align__(16) uint32_t g_ql[Mrows*32];   // permuted cols, bf16 lo
__device__ __align__(16) uint32_t g_kh[Mrows*32];   // permuted
__device__ __align__(16) uint32_t g_kl[Mrows*32];   // permuted
__device__ __align__(16) uint32_t g_vth[Mrows*32];  // permuted V^T tiles [tile][hd][s2]
__device__ __align__(16) uint32_t g_vtl[Mrows*32];
__device__ __align__(16) uint32_t g_wbh[192*512];   // permuted
__device__ __align__(16) uint32_t g_wbl[192*512];   // permuted
__device__ __align__(16) uint32_t g_wrh[1024*32];   // permuted (outproj, now LDS.64)
__device__ __align__(16) uint32_t g_wrl[1024*32];
__device__ __align__(16) float g_po[Mrows*HD];      // SINGLE accumulator (red.add)
__device__ __align__(16) float g_pl[Mrows];

// ---------------------------------------------------------------------------
__device__ __forceinline__ void mma_bf16(float4& c,
                                         uint32_t a0, uint32_t a1, uint32_t a2, uint32_t a3,
                                         uint32_t b0, uint32_t b1) {
    asm volatile(
        "mma.sync.aligned.m16n8k16.row.col.f32.bf16.bf16.f32 "
        "{%0,%1,%2,%3}, {%4,%5,%6,%7}, {%8,%9}, {%0,%1,%2,%3};"
        : "+f"(c.x), "+f"(c.y), "+f"(c.z), "+f"(c.w)
        : "r"(a0), "r"(a1), "r"(a2), "r"(a3), "r"(b0), "r"(b1));
}

__device__ __forceinline__ void bsplit2(float a0, float a1, uint32_t& h, uint32_t& l) {
    __nv_bfloat162 hh = __floats2bfloat162_rn(a0, a1);
    float r0 = a0 - __bfloat162float(hh.x);
    float r1 = a1 - __bfloat162float(hh.y);
    __nv_bfloat162 ll = __floats2bfloat162_rn(r0, r1);
    h = *reinterpret_cast<uint32_t*>(&hh);
    l = *reinterpret_cast<uint32_t*>(&ll);
}

__device__ __forceinline__ float ex2(float x) {
    float y;
    asm("ex2.approx.ftz.f32 %0, %1;" : "=f"(y) : "f"(x));
    return y;
}

__device__ __forceinline__ void cp16(uint32_t dst, const void* src) {
    asm volatile("cp.async.cg.shared.global [%0], [%1], 16;" :: "r"(dst), "l"(src));
}
__device__ __forceinline__ void cp_commit() {
    asm volatile("cp.async.commit_group;");
}
__device__ __forceinline__ void cp_wait0() {
    asm volatile("cp.async.wait_group 0;");
}

// ---------------------------------------------------------------------------
// Kernel 0: pre-split weights (ALL permuted) + fold W_out + zero accumulators
// ---------------------------------------------------------------------------
__global__ void prep_kernel(const float* __restrict__ Wq, const float* __restrict__ Wk,
                            const float* __restrict__ Wv, const float* __restrict__ Wout) {
    int idx = blockIdx.x * 256 + threadIdx.x;
    if (idx < 98304) {
        int n = idx >> 9, k2 = idx & 511;
        const float* w = (n < 64) ? Wq : ((n < 128) ? Wk : Wv);
        int r = n & 63;
        float a0 = w[(size_t)r * 1024 + 2 * k2];
        float a1 = w[(size_t)r * 1024 + 2 * k2 + 1];
        uint32_t h, l; bsplit2(a0, a1, h, l);
        int pidx = (n << 9) | PC(k2);
        g_wbh[pidx] = h; g_wbl[pidx] = l;
    } else if (idx < 131072) {
        int j = idx - 98304;
        int o = j >> 5, d2 = j & 31;
        float s0 = 0.f, s1 = 0.f;
#pragma unroll
        for (int h = 0; h < 16; h++) {
            s0 += Wout[(size_t)o * 1024 + h * 64 + 2 * d2];
            s1 += Wout[(size_t)o * 1024 + h * 64 + 2 * d2 + 1];
        }
        uint32_t h, l; bsplit2(s0, s1, h, l);
        int pj = (o << 5) | PC(d2);          // permuted for outproj LDS.64
        g_wrh[pj] = h; g_wrl[pj] = l;
    } else {
        int z = idx - 131072;
        float4 zero = make_float4(0.f, 0.f, 0.f, 0.f);
        if (z < 131072) ((float4*)g_po)[z] = zero;
        else            ((float4*)g_pl)[z - 131072] = zero;
    }
}

// ---------------------------------------------------------------------------
// Kernel 1: fused QKV (R13 config: grid 128, CTA 64 x 192, block 512,
// 16 warps = 4m x 4col, warp 16r x 48c). LDS.64 fragments, permuted layout.
// V transpose+split fused in epilogue.
// ---------------------------------------------------------------------------
#define QKV_ABUF (2*64*FPAD)
#define QKV_BBUF (2*192*FPAD)
#define QKV_B0   (2*QKV_ABUF)
#define QKV_SMEM ((2*QKV_ABUF + 2*QKV_BBUF) * 4)
#define VSTR 66   // f32 stride of the staged V tile

__global__ void __launch_bounds__(512) qkv_fused(const float* __restrict__ emb) {
    extern __shared__ uint32_t smu[];
    const uint32_t sb = (uint32_t)__cvta_generic_to_shared(smu);

    const int m0 = blockIdx.x * 64;
    const int tid = threadIdx.x;
    const int lane = tid & 31;
    const int w = tid >> 5;
    const int wm = (w & 3) * 16;
    const int colbase = (w >> 2) * 48;
    const int g = lane >> 2, q = lane & 3;

    float4 acc[6];
#pragma unroll
    for (int nb = 0; nb < 6; nb++) acc[nb] = make_float4(0.f, 0.f, 0.f, 0.f);

    const int arow0 = tid >> 4,            ac0 = tid & 15;
    const int arow1 = (tid + 512) >> 4,    ac1 = (tid + 512) & 15;

    float4 aR0 = *(const float4*)(emb + (size_t)(m0 + arow0) * Ee + ac0 * 4);
    float4 aR1 = *(const float4*)(emb + (size_t)(m0 + arow1) * Ee + ac1 * 4);
#pragma unroll
    for (int i = 0; i < 6; i++) {
        const uint32_t* gp = (i < 3) ? g_wbh : g_wbl;
        int rem = tid + (i % 3) * 512;
        int row = rem >> 3, c = rem & 7;
        uint32_t dst = sb + (QKV_B0 + (i < 3 ? 0 : 192 * FPAD) + row * FPAD + c * 4) * 4;
        cp16(dst, gp + (size_t)row * 512 + c * 4);
    }
    cp_commit();

    for (int kt = 0; kt < 16; kt++) {
        const int buf = kt & 1;
        uint32_t* Ah = smu + buf * QKV_ABUF;
        uint32_t* Al = Ah + 64 * FPAD;
        uint32_t* Bh = smu + QKV_B0 + buf * QKV_BBUF;
        uint32_t* Bl = Bh + 192 * FPAD;

        {   // store prefetched A regs (permuted u32 cols)
            uint32_t h0, l0, h1, l1;
            const int p00 = PC(2 * ac0), p01 = PC(2 * ac0 + 1);
            const int p10 = PC(2 * ac1), p11 = PC(2 * ac1 + 1);
            bsplit2(aR0.x, aR0.y, h0, l0);
            bsplit2(aR0.z, aR0.w, h1, l1);
            Ah[arow0 * FPAD + p00] = h0; Ah[arow0 * FPAD + p01] = h1;
            Al[arow0 * FPAD + p00] = l0; Al[arow0 * FPAD + p01] = l1;
            bsplit2(aR1.x, aR1.y, h0, l0);
            bsplit2(aR1.z, aR1.w, h1, l1);
            Ah[arow1 * FPAD + p10] = h0; Ah[arow1 * FPAD + p11] = h1;
            Al[arow1 * FPAD + p10] = l0; Al[arow1 * FPAD + p11] = l1;
        }
        cp_wait0();
        __syncthreads();

        if (kt < 15) {
            const int kn = (kt + 1) * 64;
            aR0 = *(const float4*)(emb + (size_t)(m0 + arow0) * Ee + kn + ac0 * 4);
            aR1 = *(const float4*)(emb + (size_t)(m0 + arow1) * Ee + kn + ac1 * 4);
            const int nbuf = buf ^ 1;
#pragma unroll
            for (int i = 0; i < 6; i++) {
                const uint32_t* gp = (i < 3) ? g_wbh : g_wbl;
                int rem = tid + (i % 3) * 512;
                int row = rem >> 3, c = rem & 7;
                uint32_t dst = sb + (QKV_B0 + nbuf * QKV_BBUF
                                     + (i < 3 ? 0 : 192 * FPAD) + row * FPAD + c * 4) * 4;
                cp16(dst, gp + (size_t)row * 512 + (kt + 1) * 32 + c * 4);
            }
            cp_commit();
        }

#pragma unroll
        for (int ks = 0; ks < 4; ks++) {
            const int kb2 = ks * 8 + 2 * q;
            uint2 a_h0 = *(const uint2*)&Ah[(wm + g) * FPAD + kb2];
            uint2 a_h1 = *(const uint2*)&Ah[(wm + g + 8) * FPAD + kb2];
            uint2 a_l0 = *(const uint2*)&Al[(wm + g) * FPAD + kb2];
            uint2 a_l1 = *(const uint2*)&Al[(wm + g + 8) * FPAD + kb2];
#pragma unroll
            for (int nb = 0; nb < 6; nb++) {
                const int n = colbase + nb * 8 + g;
                uint2 bh = *(const uint2*)&Bh[n * FPAD + kb2];
                uint2 bl = *(const uint2*)&Bl[n * FPAD + kb2];
                mma_bf16(acc[nb], a_h0.x, a_h1.x, a_h0.y, a_h1.y, bh.x, bh.y);
                mma_bf16(acc[nb], a_h0.x, a_h1.x, a_h0.y, a_h1.y, bl.x, bl.y);
                mma_bf16(acc[nb], a_l0.x, a_l1.x, a_l0.y, a_l1.y, bh.x, bh.y);
            }
        }
        __syncthreads();
    }

    // epilogue: Q/K -> gmem (hi+lo, permuted); V -> smem stage
    float* Vsm = (float*)smu;
    const size_t r0 = m0 + wm + g;
    const int rowl = wm + g;
#pragma unroll
    for (int nb = 0; nb < 6; nb++) {
        int gcol = colbase + nb * 8 + 2 * q;
        int sec = gcol >> 6;
        int lc = gcol & 63;
        int pj = PC(lc >> 1);
        float4 c = acc[nb];
        if (sec == 0) {
            uint32_t h, l;
            bsplit2(c.x * QSCALE, c.y * QSCALE, h, l);
            g_qh[r0 * 32 + pj] = h; g_ql[r0 * 32 + pj] = l;
            bsplit2(c.z * QSCALE, c.w * QSCALE, h, l);
            g_qh[(r0 + 8) * 32 + pj] = h; g_ql[(r0 + 8) * 32 + pj] = l;
        } else if (sec == 1) {
            uint32_t h, l;
            bsplit2(c.x, c.y, h, l);
            g_kh[r0 * 32 + pj] = h; g_kl[r0 * 32 + pj] = l;
            bsplit2(c.z, c.w, h, l);
            g_kh[(r0 + 8) * 32 + pj] = h; g_kl[(r0 + 8) * 32 + pj] = l;
        } else {
            Vsm[lc * VSTR + rowl]           = c.x;
            Vsm[(lc + 1) * VSTR + rowl]     = c.y;
            Vsm[lc * VSTR + rowl + 8]       = c.z;
            Vsm[(lc + 1) * VSTR + rowl + 8] = c.w;
        }
    }
    __syncthreads();

#pragma unroll
    for (int i = 0; i < 4; i++) {
        int j = tid + i * 512;
        int hd = j >> 5, s2 = j & 31;
        float v0 = Vsm[hd * VSTR + 2 * s2];
        float v1 = Vsm[hd * VSTR + 2 * s2 + 1];
        uint32_t h, l; bsplit2(v0, v1, h, l);
        int pidx = (blockIdx.x << 11) | (hd << 5) | PC(s2);
        g_vth[pidx] = h;
        g_vtl[pidx] = l;
    }
}

// ---------------------------------------------------------------------------
// Kernel 2: flash attention (unchanged from R13). 3xBF16, BQ=128, balanced
// variable split-KV, cp.async double-buffer, P in regs, no-max softmax,
// RED.ADD epilogue.
// ---------------------------------------------------------------------------
#define FL_KVBUF (4*64*FPAD)
#define FL_SMEM  ((2*FL_KVBUF) * 4)

__device__ __forceinline__ void fl_prefetch(uint32_t sb, int bufoff, size_t gbase, int tid) {
#pragma unroll
    for (int i = 0; i < 8; i++) {
        const uint32_t* gp = (i < 2) ? g_kh : (i < 4) ? g_kl : (i < 6) ? g_vth : g_vtl;
        int rem = tid + (i & 1) * 256;
        int row = rem >> 3, c = rem & 7;
        uint32_t dst = sb + (bufoff + (i >> 1) * (64 * FPAD) + row * FPAD + c * 4) * 4;
        cp16(dst, gp + gbase + rem * 4);
    }
}

__global__ void __launch_bounds__(256, 2) flash_mma() {
    extern __shared__ uint32_t smu[];
    const uint32_t sb = (uint32_t)__cvta_generic_to_shared(smu);

    const int b = blockIdx.y;
    int bid = blockIdx.x;
    int qt = 0, P = 1;
    while (bid >= P) { bid -= P; qt++; P = (qt >> 1) + 1; }
    const int part = bid;
    const int q0 = qt * 128;
    const int tid = threadIdx.x;
    const int lane = tid & 31;
    const int wm = (tid >> 5) * 16;
    const int g = lane >> 2, q = lane & 3;

    const int nt = 2 * qt + 2;
    const int t_begin = (part * nt) / P;
    const int t_end = ((part + 1) * nt) / P;

    const size_t qrow0 = (size_t)b * Tt + q0;
    uint32_t qh[4][4], ql[4][4];
#pragma unroll
    for (int ks = 0; ks < 4; ks++) {
        const int kb2 = ks * 8 + 2 * q;
        uint2 t0 = *(const uint2*)&g_qh[(qrow0 + wm + g) * 32 + kb2];
        uint2 t1 = *(const uint2*)&g_qh[(qrow0 + wm + g + 8) * 32 + kb2];
        qh[ks][0] = t0.x; qh[ks][2] = t0.y;
        qh[ks][1] = t1.x; qh[ks][3] = t1.y;
        uint2 u0 = *(const uint2*)&g_ql[(qrow0 + wm + g) * 32 + kb2];
        uint2 u1 = *(const uint2*)&g_ql[(qrow0 + wm + g + 8) * 32 + kb2];
        ql[ks][0] = u0.x; ql[ks][2] = u0.y;
        ql[ks][1] = u1.x; ql[ks][3] = u1.y;
    }

    float l0r = 0.f, l1r = 0.f;
    float4 o[8];
#pragma unroll
    for (int nb = 0; nb < 8; nb++) o[nb] = make_float4(0.f, 0.f, 0.f, 0.f);

    fl_prefetch(sb, 0, ((size_t)b * Tt + t_begin * 64) * 32, tid);
    cp_commit();

    int buf = 0;
    for (int t = t_begin; t < t_end; t++) {
        const int k0 = t * 64;
        cp_wait0();
        __syncthreads();
        if (t + 1 < t_end) {
            fl_prefetch(sb, (buf ^ 1) * FL_KVBUF, ((size_t)b * Tt + (t + 1) * 64) * 32, tid);
            cp_commit();
        }
        uint32_t* Kh  = smu + buf * FL_KVBUF;
        uint32_t* Kl  = Kh + 64 * FPAD;
        uint32_t* Vth = Kh + 2 * 64 * FPAD;
        uint32_t* Vtl = Kh + 3 * 64 * FPAD;

        float4 s[8];
#pragma unroll
        for (int nb = 0; nb < 8; nb++) s[nb] = make_float4(0.f, 0.f, 0.f, 0.f);
#pragma unroll
        for (int ks = 0; ks < 4; ks++) {
            const int kb2 = ks * 8 + 2 * q;
#pragma unroll
            for (int nb = 0; nb < 8; nb++) {
                const int n = nb * 8 + g;
                uint2 kh = *(const uint2*)&Kh[n * FPAD + kb2];
                uint2 kl = *(const uint2*)&Kl[n * FPAD + kb2];
                mma_bf16(s[nb], qh[ks][0], qh[ks][1], qh[ks][2], qh[ks][3], kh.x, kh.y);
                mma_bf16(s[nb], qh[ks][0], qh[ks][1], qh[ks][2], qh[ks][3], kl.x, kl.y);
                mma_bf16(s[nb], ql[ks][0], ql[ks][1], ql[ks][2], ql[ks][3], kh.x, kh.y);
            }
        }

        if (k0 + 63 > q0 + wm) {
            const int r0g = q0 + wm + g;
#pragma unroll
            for (int nb = 0; nb < 8; nb++) {
                int c = k0 + nb * 8 + 2 * q;
                if (c > r0g)         s[nb].x = -1e30f;
                if (c + 1 > r0g)     s[nb].y = -1e30f;
                if (c > r0g + 8)     s[nb].z = -1e30f;
                if (c + 1 > r0g + 8) s[nb].w = -1e30f;
            }
        }

#pragma unroll
        for (int nb = 0; nb < 8; nb++) {
            s[nb].x = ex2(s[nb].x);
            s[nb].y = ex2(s[nb].y);
            s[nb].z = ex2(s[nb].z);
            s[nb].w = ex2(s[nb].w);
            l0r += s[nb].x + s[nb].y;
            l1r += s[nb].z + s[nb].w;
        }

#pragma unroll
        for (int ks = 0; ks < 4; ks++) {
            uint32_t ph0, pl0, ph1, pl1, ph2, pl2, ph3, pl3;
            bsplit2(s[2 * ks].x,     s[2 * ks].y,     ph0, pl0);
            bsplit2(s[2 * ks].z,     s[2 * ks].w,     ph1, pl1);
            bsplit2(s[2 * ks + 1].x, s[2 * ks + 1].y, ph2, pl2);
            bsplit2(s[2 * ks + 1].z, s[2 * ks + 1].w, ph3, pl3);
            const int kb2 = ks * 8 + 2 * q;
#pragma unroll
            for (int nb = 0; nb < 8; nb++) {
                const int n = nb * 8 + g;
                uint2 vh = *(const uint2*)&Vth[n * FPAD + kb2];
                uint2 vl = *(const uint2*)&Vtl[n * FPAD + kb2];
                mma_bf16(o[nb], ph0, ph1, ph2, ph3, vh.x, vh.y);
                mma_bf16(o[nb], ph0, ph1, ph2, ph3, vl.x, vl.y);
                mma_bf16(o[nb], pl0, pl1, pl2, pl3, vh.x, vh.y);
            }
        }
        buf ^= 1;
    }

    l0r += __shfl_xor_sync(0xffffffffu, l0r, 1);
    l0r += __shfl_xor_sync(0xffffffffu, l0r, 2);
    l1r += __shfl_xor_sync(0xffffffffu, l1r, 1);
    l1r += __shfl_xor_sync(0xffffffffu, l1r, 2);

    const size_t row0 = (size_t)b * Tt + q0 + wm + g;
#pragma unroll
    for (int nb = 0; nb < 8; nb++) {
        int col = nb * 8 + 2 * q;
        atomicAdd(g_po + row0 * HD + col,           o[nb].x);
        atomicAdd(g_po + row0 * HD + col + 1,       o[nb].y);
        atomicAdd(g_po + (row0 + 8) * HD + col,     o[nb].z);
        atomicAdd(g_po + (row0 + 8) * HD + col + 1, o[nb].w);
    }
    if (q == 0) {
        atomicAdd(g_pl + row0, l0r);
        atomicAdd(g_pl + row0 + 8, l1r);
    }
}

// ---------------------------------------------------------------------------
// Kernel 3: out-proj 3xBF16, fused normalize+split, PERMUTED LDS.64 layout.
// CTA 128x256, block 1024 = 32 warps (8m x 4col), warp = 16r x 64c, nb=8.
// B staged via cp.async (overlaps A normalize). grid (64,4).
// ---------------------------------------------------------------------------
#define OUTP_SMEM ((2*128*FPAD + 2*256*FPAD) * 4)

__global__ void __launch_bounds__(1024) outproj_mma(float* __restrict__ out) {
    extern __shared__ uint32_t smu[];
    const uint32_t sb = (uint32_t)__cvta_generic_to_shared(smu);
    uint32_t* Ah = smu;
    uint32_t* Al = Ah + 128 * FPAD;
    uint32_t* Bh = Al + 128 * FPAD;
    uint32_t* Bl = Bh + 256 * FPAD;
    const uint32_t B0 = 2 * 128 * FPAD;   // u32 offset of Bh

    const int m0 = blockIdx.x * 128, n0 = blockIdx.y * 256;
    const int tid = threadIdx.x;
    const int lane = tid & 31;
    const int w = tid >> 5;
    const int wm = (w & 7) * 16;
    const int ncb = (w >> 3) * 64;
    const int g = lane >> 2, q = lane & 3;

    // B: cp.async 4096 uint4 (hi 2048 + lo 2048) -> 4 per thread (permuted gmem)
#pragma unroll
    for (int i = 0; i < 4; i++) {
        int j = tid + i * 1024;
        int half = j >= 2048;
        int rem = j - half * 2048;
        int row = rem >> 3, c = rem & 7;
        const uint32_t* gp = half ? g_wrl : g_wrh;
        uint32_t dst = sb + (B0 + half * 256 * FPAD + row * FPAD + c * 4) * 4;
        cp16(dst, gp + (size_t)(n0 + row) * 32 + c * 4);
    }
    cp_commit();

    // A: normalize po -> bf16 hi/lo split -> smem (permuted cols), overlaps B copy
    {
        const int arow = tid >> 3;
        const int aseg = (tid & 7) * 8;
        float inv = 1.f / g_pl[m0 + arow];
        const float* src = g_po + (size_t)(m0 + arow) * HD + aseg;
#pragma unroll
        for (int j = 0; j < 2; j++) {
            float4 v = *(const float4*)(src + j * 4);
            uint32_t h0, l0, h1, l1;
            bsplit2(v.x * inv, v.y * inv, h0, l0);
            bsplit2(v.z * inv, v.w * inv, h1, l1);
            int c2 = (aseg >> 1) + j * 2;
            int p0 = PC(c2), p1 = PC(c2 + 1);
            Ah[arow * FPAD + p0] = h0; Ah[arow * FPAD + p1] = h1;
            Al[arow * FPAD + p0] = l0; Al[arow * FPAD + p1] = l1;
        }
    }
    cp_wait0();
    __syncthreads();

    float4 acc[8];
#pragma unroll
    for (int nb = 0; nb < 8; nb++) acc[nb] = make_float4(0.f, 0.f, 0.f, 0.f);

#pragma unroll
    for (int ks = 0; ks < 4; ks++) {
        const int kb2 = ks * 8 + 2 * q;
        uint2 a_h0 = *(const uint2*)&Ah[(wm + g) * FPAD + kb2];
        uint2 a_h1 = *(const uint2*)&Ah[(wm + g + 8) * FPAD + kb2];
        uint2 a_l0 = *(const uint2*)&Al[(wm + g) * FPAD + kb2];
        uint2 a_l1 = *(const uint2*)&Al[(wm + g + 8) * FPAD + kb2];
#pragma unroll
        for (int nb = 0; nb < 8; nb++) {
            const int n = ncb + nb * 8 + g;
            uint2 bh = *(const uint2*)&Bh[n * FPAD + kb2];
            uint2 bl = *(const uint2*)&Bl[n * FPAD + kb2];
            mma_bf16(acc[nb], a_h0.x, a_h1.x, a_h0.y, a_h1.y, bh.x, bh.y);
            mma_bf16(acc[nb], a_h0.x, a_h1.x, a_h0.y, a_h1.y, bl.x, bl.y);
            mma_bf16(acc[nb], a_l0.x, a_l1.x, a_l0.y, a_l1.y, bh.x, bh.y);
        }
    }

    const int row0 = m0 + wm + g;
#pragma unroll
    for (int nb = 0; nb < 8; nb++) {
        int col = n0 + ncb + nb * 8 + 2 * q;
        *(float2*)(out + (size_t)row0 * 1024 + col)       = make_float2(acc[nb].x, acc[nb].y);
        *(float2*)(out + (size_t)(row0 + 8) * 1024 + col) = make_float2(acc[nb].z, acc[nb].w);
    }
}

// ---------------------------------------------------------------------------
extern "C" void kernel_launch(void* const* d_in, const int* in_sizes, int n_in,
                              void* d_out, int out_size) {
    (void)in_sizes; (void)n_in; (void)out_size;
    const float* emb  = (const float*)d_in[0];
    const float* Wq   = (const float*)d_in[1];
    const float* Wk   = (const float*)d_in[2];
    const float* Wv   = (const float*)d_in[3];
    const float* Wout = (const float*)d_in[4];
    float* out = (float*)d_out;

    prep_kernel<<<1032, 256>>>(Wq, Wk, Wv, Wout);

    cudaFuncSetAttribute(qkv_fused, cudaFuncAttributeMaxDynamicSharedMemorySize, QKV_SMEM);
    qkv_fused<<<128, 512, QKV_SMEM>>>(emb);

    cudaFuncSetAttribute(flash_mma, cudaFuncAttributeMaxDynamicSharedMemorySize, FL_SMEM);
    flash_mma<<<dim3(72, 4), 256, FL_SMEM>>>();

    cudaFuncSetAttribute(outproj_mma, cudaFuncAttributeMaxDynamicSharedMemorySize, OUTP_SMEM);
    outproj_mma<<<dim3(64, 4), 1024, OUTP_SMEM>>>(out);
}

// round 16
// speedup vs baseline: 1.0582x; 1.0373x over previous
#include <cuda_runtime.h>
#include <cuda_bf16.h>
#include <cstdint>

#define Bb 4
#define Tt 2048
#define Ee 1024
#define HD 64
#define Mrows (Bb*Tt)
#define FPAD 36   // u32 row stride: ldmatrix 16B-chunk bank = 9n%8 = n%8 -> conflict-free
// Q pre-scale: (1/sqrt(64)) * log2(e), so softmax is a bare exp2
#define QSCALE 0.1803368801111244f
// pair-permute (Q gmem only): c -> 2*(c%4) + (c>=4)
#define PC(c) (((c) & ~7) | (((c) & 3) << 1) | (((c) >> 2) & 1))

// scratch (no cudaMalloc allowed)
__device__ __align__(16) uint32_t g_qh[Mrows*32];   // PC-permuted (flash reads frags from gmem)
__device__ __align__(16) uint32_t g_ql[Mrows*32];   // PC-permuted
__device__ __align__(16) uint32_t g_kh[Mrows*32];   // linear [row][k2]
__device__ __align__(16) uint32_t g_kl[Mrows*32];
__device__ __align__(16) uint32_t g_vth[Mrows*32];  // linear V^T tiles [tile][hd][s2]
__device__ __align__(16) uint32_t g_vtl[Mrows*32];
__device__ __align__(16) uint32_t g_wbh[192*512];   // linear
__device__ __align__(16) uint32_t g_wbl[192*512];
__device__ __align__(16) uint32_t g_wrh[1024*32];   // linear
__device__ __align__(16) uint32_t g_wrl[1024*32];
__device__ __align__(16) float g_po[Mrows*HD];      // single accumulator (red.add)
__device__ __align__(16) float g_pl[Mrows];

// ---------------------------------------------------------------------------
__device__ __forceinline__ void mma_bf16(float4& c,
                                         uint32_t a0, uint32_t a1, uint32_t a2, uint32_t a3,
                                         uint32_t b0, uint32_t b1) {
    asm volatile(
        "mma.sync.aligned.m16n8k16.row.col.f32.bf16.bf16.f32 "
        "{%0,%1,%2,%3}, {%4,%5,%6,%7}, {%8,%9}, {%0,%1,%2,%3};"
        : "+f"(c.x), "+f"(c.y), "+f"(c.z), "+f"(c.w)
        : "r"(a0), "r"(a1), "r"(a2), "r"(a3), "r"(b0), "r"(b1));
}

#define LDSM4(r, a)                                                            \
    asm volatile("ldmatrix.sync.aligned.m8n8.x4.shared.b16 {%0,%1,%2,%3}, [%4];" \
                 : "=r"((r)[0]), "=r"((r)[1]), "=r"((r)[2]), "=r"((r)[3])      \
                 : "r"(a))

__device__ __forceinline__ void bsplit2(float a0, float a1, uint32_t& h, uint32_t& l) {
    __nv_bfloat162 hh = __floats2bfloat162_rn(a0, a1);
    float r0 = a0 - __bfloat162float(hh.x);
    float r1 = a1 - __bfloat162float(hh.y);
    __nv_bfloat162 ll = __floats2bfloat162_rn(r0, r1);
    h = *reinterpret_cast<uint32_t*>(&hh);
    l = *reinterpret_cast<uint32_t*>(&ll);
}

__device__ __forceinline__ float ex2(float x) {
    float y;
    asm("ex2.approx.ftz.f32 %0, %1;" : "=f"(y) : "f"(x));
    return y;
}

__device__ __forceinline__ void cp16(uint32_t dst, const void* src) {
    asm volatile("cp.async.cg.shared.global [%0], [%1], 16;" :: "r"(dst), "l"(src));
}
__device__ __forceinline__ void cp_commit() {
    asm volatile("cp.async.commit_group;");
}
__device__ __forceinline__ void cp_wait0() {
    asm volatile("cp.async.wait_group 0;");
}

// ---------------------------------------------------------------------------
// Kernel 0: pre-split weights (linear) + fold W_out + zero accumulators
// ---------------------------------------------------------------------------
__global__ void prep_kernel(const float* __restrict__ Wq, const float* __restrict__ Wk,
                            const float* __restrict__ Wv, const float* __restrict__ Wout) {
    int idx = blockIdx.x * 256 + threadIdx.x;
    if (idx < 98304) {
        int n = idx >> 9, k2 = idx & 511;
        const float* w = (n < 64) ? Wq : ((n < 128) ? Wk : Wv);
        int r = n & 63;
        float a0 = w[(size_t)r * 1024 + 2 * k2];
        float a1 = w[(size_t)r * 1024 + 2 * k2 + 1];
        uint32_t h, l; bsplit2(a0, a1, h, l);
        g_wbh[idx] = h; g_wbl[idx] = l;
    } else if (idx < 131072) {
        int j = idx - 98304;
        int o = j >> 5, d2 = j & 31;
        float s0 = 0.f, s1 = 0.f;
#pragma unroll
        for (int h = 0; h < 16; h++) {
            s0 += Wout[(size_t)o * 1024 + h * 64 + 2 * d2];
            s1 += Wout[(size_t)o * 1024 + h * 64 + 2 * d2 + 1];
        }
        uint32_t h, l; bsplit2(s0, s1, h, l);
        g_wrh[j] = h; g_wrl[j] = l;
    } else {
        int z = idx - 131072;
        float4 zero = make_float4(0.f, 0.f, 0.f, 0.f);
        if (z < 131072) ((float4*)g_po)[z] = zero;
        else            ((float4*)g_pl)[z - 131072] = zero;
    }
}

// ---------------------------------------------------------------------------
// Kernel 1: fused QKV (grid 128, CTA 64 x 192, block 512, 16 warps = 4m x 4col,
// warp 16r x 48c). LDSM fragment loads; V transpose+split fused in epilogue.
// ---------------------------------------------------------------------------
#define QKV_ABUF (2*64*FPAD)
#define QKV_BBUF (2*192*FPAD)
#define QKV_B0   (2*QKV_ABUF)
#define QKV_SMEM ((2*QKV_ABUF + 2*QKV_BBUF) * 4)
#define VSTR 66

__global__ void __launch_bounds__(512) qkv_fused(const float* __restrict__ emb) {
    extern __shared__ uint32_t smu[];
    const uint32_t sb = (uint32_t)__cvta_generic_to_shared(smu);

    const int m0 = blockIdx.x * 64;
    const int tid = threadIdx.x;
    const int lane = tid & 31;
    const int w = tid >> 5;
    const int wm = (w & 3) * 16;
    const int colbase = (w >> 2) * 48;
    const int g = lane >> 2, q = lane & 3;
    const int lrow = lane & 7, lmat = lane >> 3;

    // per-lane LDSM byte offsets (within operand tile)
    const uint32_t laofsA = ((wm + lrow + (lmat & 1) * 8) * FPAD + (lmat >> 1) * 4) * 4;
    const uint32_t lbofs  = ((colbase + (lmat >> 1) * 8 + lrow) * FPAD + (lmat & 1) * 4) * 4;

    float4 acc[6];
#pragma unroll
    for (int nb = 0; nb < 6; nb++) acc[nb] = make_float4(0.f, 0.f, 0.f, 0.f);

    const int arow0 = tid >> 4,            ac0 = tid & 15;
    const int arow1 = (tid + 512) >> 4,    ac1 = (tid + 512) & 15;

    float4 aR0 = *(const float4*)(emb + (size_t)(m0 + arow0) * Ee + ac0 * 4);
    float4 aR1 = *(const float4*)(emb + (size_t)(m0 + arow1) * Ee + ac1 * 4);
#pragma unroll
    for (int i = 0; i < 6; i++) {
        const uint32_t* gp = (i < 3) ? g_wbh : g_wbl;
        int rem = tid + (i % 3) * 512;
        int row = rem >> 3, c = rem & 7;
        uint32_t dst = sb + (QKV_B0 + (i < 3 ? 0 : 192 * FPAD) + row * FPAD + c * 4) * 4;
        cp16(dst, gp + (size_t)row * 512 + c * 4);
    }
    cp_commit();

    for (int kt = 0; kt < 16; kt++) {
        const int buf = kt & 1;
        uint32_t* Ah = smu + buf * QKV_ABUF;
        uint32_t* Al = Ah + 64 * FPAD;

        {   // store prefetched A regs (linear pairs -> uint2)
            uint32_t h0, l0, h1, l1;
            bsplit2(aR0.x, aR0.y, h0, l0);
            bsplit2(aR0.z, aR0.w, h1, l1);
            *(uint2*)&Ah[arow0 * FPAD + 2 * ac0] = make_uint2(h0, h1);
            *(uint2*)&Al[arow0 * FPAD + 2 * ac0] = make_uint2(l0, l1);
            bsplit2(aR1.x, aR1.y, h0, l0);
            bsplit2(aR1.z, aR1.w, h1, l1);
            *(uint2*)&Ah[arow1 * FPAD + 2 * ac1] = make_uint2(h0, h1);
            *(uint2*)&Al[arow1 * FPAD + 2 * ac1] = make_uint2(l0, l1);
        }
        cp_wait0();
        __syncthreads();

        if (kt < 15) {
            const int kn = (kt + 1) * 64;
            aR0 = *(const float4*)(emb + (size_t)(m0 + arow0) * Ee + kn + ac0 * 4);
            aR1 = *(const float4*)(emb + (size_t)(m0 + arow1) * Ee + kn + ac1 * 4);
            const int nbuf = buf ^ 1;
#pragma unroll
            for (int i = 0; i < 6; i++) {
                const uint32_t* gp = (i < 3) ? g_wbh : g_wbl;
                int rem = tid + (i % 3) * 512;
                int row = rem >> 3, c = rem & 7;
                uint32_t dst = sb + (QKV_B0 + nbuf * QKV_BBUF
                                     + (i < 3 ? 0 : 192 * FPAD) + row * FPAD + c * 4) * 4;
                cp16(dst, gp + (size_t)row * 512 + (kt + 1) * 32 + c * 4);
            }
            cp_commit();
        }

        const uint32_t Ab = sb + (buf * QKV_ABUF) * 4;
        const uint32_t Bbs = sb + (QKV_B0 + buf * QKV_BBUF) * 4;
#pragma unroll
        for (int ks = 0; ks < 4; ks++) {
            uint32_t ah[4], al[4];
            LDSM4(ah, Ab + laofsA + ks * 32);
            LDSM4(al, Ab + 64 * FPAD * 4 + laofsA + ks * 32);
#pragma unroll
            for (int G = 0; G < 3; G++) {
                uint32_t bh[4], bl[4];
                uint32_t boff = Bbs + lbofs + G * (16 * FPAD * 4) + ks * 32;
                LDSM4(bh, boff);
                LDSM4(bl, boff + 192 * FPAD * 4);
                mma_bf16(acc[2*G],   ah[0], ah[1], ah[2], ah[3], bh[0], bh[1]);
                mma_bf16(acc[2*G+1], ah[0], ah[1], ah[2], ah[3], bh[2], bh[3]);
                mma_bf16(acc[2*G],   ah[0], ah[1], ah[2], ah[3], bl[0], bl[1]);
                mma_bf16(acc[2*G+1], ah[0], ah[1], ah[2], ah[3], bl[2], bl[3]);
                mma_bf16(acc[2*G],   al[0], al[1], al[2], al[3], bh[0], bh[1]);
                mma_bf16(acc[2*G+1], al[0], al[1], al[2], al[3], bh[2], bh[3]);
            }
        }
        __syncthreads();
    }

    // epilogue: Q (PC-permuted) / K (linear) -> gmem; V -> smem stage
    float* Vsm = (float*)smu;
    const size_t r0 = m0 + wm + g;
    const int rowl = wm + g;
#pragma unroll
    for (int nb = 0; nb < 6; nb++) {
        int gcol = colbase + nb * 8 + 2 * q;
        int sec = gcol >> 6;
        int lc = gcol & 63;
        float4 c = acc[nb];
        if (sec == 0) {          // Q: hi+lo, pre-scaled, PC-permuted cols
            int pj = PC(lc >> 1);
            uint32_t h, l;
            bsplit2(c.x * QSCALE, c.y * QSCALE, h, l);
            g_qh[r0 * 32 + pj] = h; g_ql[r0 * 32 + pj] = l;
            bsplit2(c.z * QSCALE, c.w * QSCALE, h, l);
            g_qh[(r0 + 8) * 32 + pj] = h; g_ql[(r0 + 8) * 32 + pj] = l;
        } else if (sec == 1) {   // K: hi+lo, linear cols
            int pj = lc >> 1;
            uint32_t h, l;
            bsplit2(c.x, c.y, h, l);
            g_kh[r0 * 32 + pj] = h; g_kl[r0 * 32 + pj] = l;
            bsplit2(c.z, c.w, h, l);
            g_kh[(r0 + 8) * 32 + pj] = h; g_kl[(r0 + 8) * 32 + pj] = l;
        } else {                 // V: stage f32 transposed in smem
            Vsm[lc * VSTR + rowl]           = c.x;
            Vsm[(lc + 1) * VSTR + rowl]     = c.y;
            Vsm[lc * VSTR + rowl + 8]       = c.z;
            Vsm[(lc + 1) * VSTR + rowl + 8] = c.w;
        }
    }
    __syncthreads();

    // cooperative V^T split (linear layout)
#pragma unroll
    for (int i = 0; i < 4; i++) {
        int j = tid + i * 512;
        int hd = j >> 5, s2 = j & 31;
        float v0 = Vsm[hd * VSTR + 2 * s2];
        float v1 = Vsm[hd * VSTR + 2 * s2 + 1];
        uint32_t h, l; bsplit2(v0, v1, h, l);
        int pidx = (blockIdx.x << 11) | (hd << 5) | s2;
        g_vth[pidx] = h;
        g_vtl[pidx] = l;
    }
}

// ---------------------------------------------------------------------------
// Kernel 2: flash attention. 3xBF16 QK^T and PV, BQ=128, balanced variable
// split-KV, cp.async double-buffer, P in regs, no-max softmax, LDSM B-frags,
// RED.ADD epilogue.
// ---------------------------------------------------------------------------
#define FL_KVBUF (4*64*FPAD)
#define FL_SMEM  ((2*FL_KVBUF) * 4)

__device__ __forceinline__ void fl_prefetch(uint32_t sb, int bufoff, size_t gbase, int tid) {
#pragma unroll
    for (int i = 0; i < 8; i++) {
        const uint32_t* gp = (i < 2) ? g_kh : (i < 4) ? g_kl : (i < 6) ? g_vth : g_vtl;
        int rem = tid + (i & 1) * 256;
        int row = rem >> 3, c = rem & 7;
        uint32_t dst = sb + (bufoff + (i >> 1) * (64 * FPAD) + row * FPAD + c * 4) * 4;
        cp16(dst, gp + gbase + rem * 4);
    }
}

__global__ void __launch_bounds__(256, 2) flash_mma() {
    extern __shared__ uint32_t smu[];
    const uint32_t sb = (uint32_t)__cvta_generic_to_shared(smu);

    const int b = blockIdx.y;
    int bid = blockIdx.x;
    int qt = 0, P = 1;
    while (bid >= P) { bid -= P; qt++; P = (qt >> 1) + 1; }
    const int part = bid;
    const int q0 = qt * 128;
    const int tid = threadIdx.x;
    const int lane = tid & 31;
    const int wm = (tid >> 5) * 16;
    const int g = lane >> 2, q = lane & 3;
    const int lrow = lane & 7, lmat = lane >> 3;
    const uint32_t lofsB = (((lmat >> 1) * 8 + lrow) * FPAD + (lmat & 1) * 4) * 4;

    const int nt = 2 * qt + 2;
    const int t_begin = (part * nt) / P;
    const int t_end = ((part + 1) * nt) / P;

    const size_t qrow0 = (size_t)b * Tt + q0;
    uint32_t qh[4][4], ql[4][4];
#pragma unroll
    for (int ks = 0; ks < 4; ks++) {
        const int kb2 = ks * 8 + 2 * q;
        uint2 t0 = *(const uint2*)&g_qh[(qrow0 + wm + g) * 32 + kb2];
        uint2 t1 = *(const uint2*)&g_qh[(qrow0 + wm + g + 8) * 32 + kb2];
        qh[ks][0] = t0.x; qh[ks][2] = t0.y;
        qh[ks][1] = t1.x; qh[ks][3] = t1.y;
        uint2 u0 = *(const uint2*)&g_ql[(qrow0 + wm + g) * 32 + kb2];
        uint2 u1 = *(const uint2*)&g_ql[(qrow0 + wm + g + 8) * 32 + kb2];
        ql[ks][0] = u0.x; ql[ks][2] = u0.y;
        ql[ks][1] = u1.x; ql[ks][3] = u1.y;
    }

    float l0r = 0.f, l1r = 0.f;
    float4 o[8];
#pragma unroll
    for (int nb = 0; nb < 8; nb++) o[nb] = make_float4(0.f, 0.f, 0.f, 0.f);

    fl_prefetch(sb, 0, ((size_t)b * Tt + t_begin * 64) * 32, tid);
    cp_commit();

    int buf = 0;
    for (int t = t_begin; t < t_end; t++) {
        const int k0 = t * 64;
        cp_wait0();
        __syncthreads();
        if (t + 1 < t_end) {
            fl_prefetch(sb, (buf ^ 1) * FL_KVBUF, ((size_t)b * Tt + (t + 1) * 64) * 32, tid);
            cp_commit();
        }
        const uint32_t Kb = sb + (buf * FL_KVBUF) * 4 + lofsB;

        // S = Q K^T  (3x), K fragments via LDSM
        float4 s[8];
#pragma unroll
        for (int nb = 0; nb < 8; nb++) s[nb] = make_float4(0.f, 0.f, 0.f, 0.f);
#pragma unroll
        for (int ks = 0; ks < 4; ks++) {
#pragma unroll
            for (int G = 0; G < 4; G++) {
                uint32_t kh[4], kl[4];
                uint32_t off = Kb + G * (16 * FPAD * 4) + ks * 32;
                LDSM4(kh, off);
                LDSM4(kl, off + 64 * FPAD * 4);
                mma_bf16(s[2*G],   qh[ks][0], qh[ks][1], qh[ks][2], qh[ks][3], kh[0], kh[1]);
                mma_bf16(s[2*G+1], qh[ks][0], qh[ks][1], qh[ks][2], qh[ks][3], kh[2], kh[3]);
                mma_bf16(s[2*G],   qh[ks][0], qh[ks][1], qh[ks][2], qh[ks][3], kl[0], kl[1]);
                mma_bf16(s[2*G+1], qh[ks][0], qh[ks][1], qh[ks][2], qh[ks][3], kl[2], kl[3]);
                mma_bf16(s[2*G],   ql[ks][0], ql[ks][1], ql[ks][2], ql[ks][3], kh[0], kh[1]);
                mma_bf16(s[2*G+1], ql[ks][0], ql[ks][1], ql[ks][2], ql[ks][3], kh[2], kh[3]);
            }
        }

        // causal mask
        if (k0 + 63 > q0 + wm) {
            const int r0g = q0 + wm + g;
#pragma unroll
            for (int nb = 0; nb < 8; nb++) {
                int c = k0 + nb * 8 + 2 * q;
                if (c > r0g)         s[nb].x = -1e30f;
                if (c + 1 > r0g)     s[nb].y = -1e30f;
                if (c > r0g + 8)     s[nb].z = -1e30f;
                if (c + 1 > r0g + 8) s[nb].w = -1e30f;
            }
        }

        // p = exp2(s); per-lane row sums
#pragma unroll
        for (int nb = 0; nb < 8; nb++) {
            s[nb].x = ex2(s[nb].x);
            s[nb].y = ex2(s[nb].y);
            s[nb].z = ex2(s[nb].z);
            s[nb].w = ex2(s[nb].w);
            l0r += s[nb].x + s[nb].y;
            l1r += s[nb].z + s[nb].w;
        }

        // O += P V  (3x), V fragments via LDSM, P packed from S regs
        const uint32_t Vb = Kb + 2 * 64 * FPAD * 4;
#pragma unroll
        for (int ks = 0; ks < 4; ks++) {
            uint32_t ph0, pl0, ph1, pl1, ph2, pl2, ph3, pl3;
            bsplit2(s[2 * ks].x,     s[2 * ks].y,     ph0, pl0);
            bsplit2(s[2 * ks].z,     s[2 * ks].w,     ph1, pl1);
            bsplit2(s[2 * ks + 1].x, s[2 * ks + 1].y, ph2, pl2);
            bsplit2(s[2 * ks + 1].z, s[2 * ks + 1].w, ph3, pl3);
#pragma unroll
            for (int G = 0; G < 4; G++) {
                uint32_t vh[4], vl[4];
                uint32_t off = Vb + G * (16 * FPAD * 4) + ks * 32;
                LDSM4(vh, off);
                LDSM4(vl, off + 64 * FPAD * 4);
                mma_bf16(o[2*G],   ph0, ph1, ph2, ph3, vh[0], vh[1]);
                mma_bf16(o[2*G+1], ph0, ph1, ph2, ph3, vh[2], vh[3]);
                mma_bf16(o[2*G],   ph0, ph1, ph2, ph3, vl[0], vl[1]);
                mma_bf16(o[2*G+1], ph0, ph1, ph2, ph3, vl[2], vl[3]);
                mma_bf16(o[2*G],   pl0, pl1, pl2, pl3, vh[0], vh[1]);
                mma_bf16(o[2*G+1], pl0, pl1, pl2, pl3, vh[2], vh[3]);
            }
        }
        buf ^= 1;
    }

    l0r += __shfl_xor_sync(0xffffffffu, l0r, 1);
    l0r += __shfl_xor_sync(0xffffffffu, l0r, 2);
    l1r += __shfl_xor_sync(0xffffffffu, l1r, 1);
    l1r += __shfl_xor_sync(0xffffffffu, l1r, 2);

    const size_t row0 = (size_t)b * Tt + q0 + wm + g;
#pragma unroll
    for (int nb = 0; nb < 8; nb++) {
        int col = nb * 8 + 2 * q;
        atomicAdd(g_po + row0 * HD + col,           o[nb].x);
        atomicAdd(g_po + row0 * HD + col + 1,       o[nb].y);
        atomicAdd(g_po + (row0 + 8) * HD + col,     o[nb].z);
        atomicAdd(g_po + (row0 + 8) * HD + col + 1, o[nb].w);
    }
    if (q == 0) {
        atomicAdd(g_pl + row0, l0r);
        atomicAdd(g_pl + row0 + 8, l1r);
    }
}

// ---------------------------------------------------------------------------
// Kernel 3: out-proj 3xBF16, fused normalize+split, LDSM fragment loads.
// CTA 128x256, block 1024 = 32 warps (8m x 4col), warp = 16r x 64c, nb=8.
// grid (64,4).
// ---------------------------------------------------------------------------
#define OUTP_SMEM ((2*128*FPAD + 2*256*FPAD) * 4)

__global__ void __launch_bounds__(1024) outproj_mma(float* __restrict__ out) {
    extern __shared__ uint32_t smu[];
    const uint32_t sb = (uint32_t)__cvta_generic_to_shared(smu);
    uint32_t* Ah = smu;
    uint32_t* Al = Ah + 128 * FPAD;
    const uint32_t B0 = 2 * 128 * FPAD;   // u32 offset of Bh

    const int m0 = blockIdx.x * 128, n0 = blockIdx.y * 256;
    const int tid = threadIdx.x;
    const int lane = tid & 31;
    const int w = tid >> 5;
    const int wm = (w & 7) * 16;
    const int ncb = (w >> 3) * 64;
    const int g = lane >> 2, q = lane & 3;
    const int lrow = lane & 7, lmat = lane >> 3;
    const uint32_t laofsA = ((wm + lrow + (lmat & 1) * 8) * FPAD + (lmat >> 1) * 4) * 4;
    const uint32_t lbofs  = ((ncb + (lmat >> 1) * 8 + lrow) * FPAD + (lmat & 1) * 4) * 4;

    // B: cp.async 4096 uint4 -> 4 per thread
#pragma unroll
    for (int i = 0; i < 4; i++) {
        int j = tid + i * 1024;
        int half = j >= 2048;
        int rem = j - half * 2048;
        int row = rem >> 3, c = rem & 7;
        const uint32_t* gp = half ? g_wrl : g_wrh;
        uint32_t dst = sb + (B0 + half * 256 * FPAD + row * FPAD + c * 4) * 4;
        cp16(dst, gp + (size_t)(n0 + row) * 32 + c * 4);
    }
    cp_commit();

    // A: normalize po -> bf16 hi/lo split -> smem (linear), overlaps B copy
    {
        const int arow = tid >> 3;
        const int aseg = (tid & 7) * 8;
        float inv = 1.f / g_pl[m0 + arow];
        const float* src = g_po + (size_t)(m0 + arow) * HD + aseg;
#pragma unroll
        for (int j = 0; j < 2; j++) {
            float4 v = *(const float4*)(src + j * 4);
            uint32_t h0, l0, h1, l1;
            bsplit2(v.x * inv, v.y * inv, h0, l0);
            bsplit2(v.z * inv, v.w * inv, h1, l1);
            int c2 = (aseg >> 1) + j * 2;
            *(uint2*)&Ah[arow * FPAD + c2] = make_uint2(h0, h1);
            *(uint2*)&Al[arow * FPAD + c2] = make_uint2(l0, l1);
        }
    }
    cp_wait0();
    __syncthreads();

    float4 acc[8];
#pragma unroll
    for (int nb = 0; nb < 8; nb++) acc[nb] = make_float4(0.f, 0.f, 0.f, 0.f);

    const uint32_t Ab = sb;
    const uint32_t Bbs = sb + B0 * 4;
#pragma unroll
    for (int ks = 0; ks < 4; ks++) {
        uint32_t ah[4], al[4];
        LDSM4(ah, Ab + laofsA + ks * 32);
        LDSM4(al, Ab + 128 * FPAD * 4 + laofsA + ks * 32);
#pragma unroll
        for (int G = 0; G < 4; G++) {
            uint32_t bh[4], bl[4];
            uint32_t boff = Bbs + lbofs + G * (16 * FPAD * 4) + ks * 32;
            LDSM4(bh, boff);
            LDSM4(bl, boff + 256 * FPAD * 4);
            mma_bf16(acc[2*G],   ah[0], ah[1], ah[2], ah[3], bh[0], bh[1]);
            mma_bf16(acc[2*G+1], ah[0], ah[1], ah[2], ah[3], bh[2], bh[3]);
            mma_bf16(acc[2*G],   ah[0], ah[1], ah[2], ah[3], bl[0], bl[1]);
            mma_bf16(acc[2*G+1], ah[0], ah[1], ah[2], ah[3], bl[2], bl[3]);
            mma_bf16(acc[2*G],   al[0], al[1], al[2], al[3], bh[0], bh[1]);
            mma_bf16(acc[2*G+1], al[0], al[1], al[2], al[3], bh[2], bh[3]);
        }
    }

    const int row0 = m0 + wm + g;
#pragma unroll
    for (int nb = 0; nb < 8; nb++) {
        int col = n0 + ncb + nb * 8 + 2 * q;
        *(float2*)(out + (size_t)row0 * 1024 + col)       = make_float2(acc[nb].x, acc[nb].y);
        *(float2*)(out + (size_t)(row0 + 8) * 1024 + col) = make_float2(acc[nb].z, acc[nb].w);
    }
}

// ---------------------------------------------------------------------------
extern "C" void kernel_launch(void* const* d_in, const int* in_sizes, int n_in,
                              void* d_out, int out_size) {
    (void)in_sizes; (void)n_in; (void)out_size;
    const float* emb  = (const float*)d_in[0];
    const float* Wq   = (const float*)d_in[1];
    const float* Wk   = (const float*)d_in[2];
    const float* Wv   = (const float*)d_in[3];
    const float* Wout = (const float*)d_in[4];
    float* out = (float*)d_out;

    prep_kernel<<<1032, 256>>>(Wq, Wk, Wv, Wout);

    cudaFuncSetAttribute(qkv_fused, cudaFuncAttributeMaxDynamicSharedMemorySize, QKV_SMEM);
    qkv_fused<<<128, 512, QKV_SMEM>>>(emb);

    cudaFuncSetAttribute(flash_mma, cudaFuncAttributeMaxDynamicSharedMemorySize, FL_SMEM);
    flash_mma<<<dim3(72, 4), 256, FL_SMEM>>>();

    cudaFuncSetAttribute(outproj_mma, cudaFuncAttributeMaxDynamicSharedMemorySize, OUTP_SMEM);
    outproj_mma<<<dim3(64, 4), 1024, OUTP_SMEM>>>(out);
}